// round 4
// baseline (speedup 1.0000x reference)
#include <cuda_runtime.h>
#include <stdint.h>

#define BB 16
#define PP 8192
#define MM 128
#define KNN 16
#define DD 768
#define QQ (BB*MM)      // 2048 queries/tokens
#define RR (QQ*KNN)     // 32768 gathered rows

// ---------------- scratch (device globals; no allocation allowed) ----------------
__device__ float g_cent[QQ*4];
__device__ int   g_knn[RR];
__device__ float g_bufA[(size_t)RR*768];
__device__ float g_bufB[(size_t)RR*768];
__device__ float g_pool[(size_t)QQ*DD];
__device__ float g_h[(size_t)QQ*DD];

// ---------------- FPS: one block per batch, points register-resident -------------
__global__ __launch_bounds__(1024) void fps_kernel(const float* __restrict__ coords,
                                                   float* __restrict__ cent_out2)
{
    int b = blockIdx.x;
    int tid = threadIdx.x;
    float px[8], py[8], pz[8], pw[8], dmin[8];
#pragma unroll
    for (int i = 0; i < 8; i++) {
        int p = tid + i * 1024;
        const float* c = coords + ((size_t)b * PP + p) * 5;
        px[i] = c[1]; py[i] = c[2]; pz[i] = c[3]; pw[i] = c[4];
        dmin[i] = 1e30f;
    }
    __shared__ float last[4];
    __shared__ unsigned long long red[32];
    __shared__ int cur_s;
    int cur = 0;
    for (int m = 0; m < MM; m++) {
        if (tid == (cur & 1023)) {
            int i = cur >> 10;
            last[0] = px[i]; last[1] = py[i]; last[2] = pz[i]; last[3] = pw[i];
            float* o  = g_cent + ((size_t)b * MM + m) * 4;
            o[0] = px[i]; o[1] = py[i]; o[2] = pz[i]; o[3] = pw[i];
            float* o2 = cent_out2 + ((size_t)b * MM + m) * 4;
            o2[0] = px[i]; o2[1] = py[i]; o2[2] = pz[i]; o2[3] = pw[i];
        }
        __syncthreads();
        if (m == MM - 1) break;
        float lx = last[0], ly = last[1], lz = last[2], lw = last[3];
        unsigned long long best = 0ull;
#pragma unroll
        for (int i = 0; i < 8; i++) {
            // exact XLA order: (((dx*dx + dy*dy) + dz*dz) + dw*dw), no FMA contraction
            float dx = __fsub_rn(px[i], lx);
            float dy = __fsub_rn(py[i], ly);
            float dz = __fsub_rn(pz[i], lz);
            float dw = __fsub_rn(pw[i], lw);
            float d = __fadd_rn(__fadd_rn(__fadd_rn(__fmul_rn(dx,dx), __fmul_rn(dy,dy)),
                                          __fmul_rn(dz,dz)), __fmul_rn(dw,dw));
            float dm = fminf(dmin[i], d);
            dmin[i] = dm;
            // key: maximize dmin; on ties pick smallest global index (argmax = first max)
            unsigned long long key = ((unsigned long long)__float_as_uint(dm) << 32)
                                   | (unsigned)(0x7FFFFFFF - (tid + i * 1024));
            if (key > best) best = key;
        }
        for (int off = 16; off; off >>= 1) {
            unsigned long long o = __shfl_down_sync(0xFFFFFFFFu, best, off);
            if (o > best) best = o;
        }
        if ((tid & 31) == 0) red[tid >> 5] = best;
        __syncthreads();
        if (tid < 32) {
            unsigned long long v = red[tid];
            for (int off = 16; off; off >>= 1) {
                unsigned long long o = __shfl_down_sync(0xFFFFFFFFu, v, off);
                if (o > v) v = o;
            }
            if (tid == 0) cur_s = 0x7FFFFFFF - (int)(v & 0xFFFFFFFFu);
        }
        __syncthreads();
        cur = cur_s;
    }
}

// ---------------- kNN: one block per centroid, keys in 64KB smem ------------------
__global__ __launch_bounds__(256) void knn_kernel(const float* __restrict__ coords,
                                                  int* __restrict__ knn)
{
    extern __shared__ unsigned long long keys[];   // PP entries
    int m = blockIdx.x, b = blockIdx.y;
    int tid = threadIdx.x;
    const float* c = g_cent + ((size_t)b * MM + m) * 4;
    float c0 = c[0], c1 = c[1], c2 = c[2], c3 = c[3];
    float cen2 = __fadd_rn(__fadd_rn(__fadd_rn(__fmul_rn(c0,c0), __fmul_rn(c1,c1)),
                                     __fmul_rn(c2,c2)), __fmul_rn(c3,c3));
    for (int p = tid; p < PP; p += 256) {
        const float* q = coords + ((size_t)b * PP + p) * 5;
        float x0 = q[1], x1 = q[2], x2 = q[3], x3 = q[4];
        float pts2 = __fadd_rn(__fadd_rn(__fadd_rn(__fmul_rn(x0,x0), __fmul_rn(x1,x1)),
                                         __fmul_rn(x2,x2)), __fmul_rn(x3,x3));
        float dot  = __fadd_rn(__fadd_rn(__fadd_rn(__fmul_rn(c0,x0), __fmul_rn(c1,x1)),
                                         __fmul_rn(c2,x2)), __fmul_rn(c3,x3));
        float d2 = __fsub_rn(__fadd_rn(cen2, pts2), __fmul_rn(2.0f, dot));
        unsigned u = __float_as_uint(d2);
        u = (u & 0x80000000u) ? ~u : (u | 0x80000000u);   // order-preserving map
        keys[p] = ((unsigned long long)u << 32) | (unsigned)p;
    }
    __syncthreads();
    __shared__ unsigned long long red[8];
    for (int k = 0; k < KNN; k++) {
        unsigned long long best = ~0ull;
        for (int p = tid; p < PP; p += 256) {
            unsigned long long v = keys[p];
            if (v < best) best = v;
        }
        for (int off = 16; off; off >>= 1) {
            unsigned long long o = __shfl_down_sync(0xFFFFFFFFu, best, off);
            if (o < best) best = o;
        }
        if ((tid & 31) == 0) red[tid >> 5] = best;
        __syncthreads();
        if (tid == 0) {
            unsigned long long v = red[0];
            for (int w = 1; w < 8; w++) if (red[w] < v) v = red[w];
            int idx = (int)(v & 0xFFFFFFFFu);
            knn[((size_t)b * MM + m) * KNN + k] = idx;
            keys[idx] = ~0ull;
        }
        __syncthreads();
    }
}

// ---------------- gather + layer1 (6 -> 256, relu) --------------------------------
__global__ __launch_bounds__(256) void gather_mlp1(const float* __restrict__ feats,
                                                   const float* __restrict__ W1,
                                                   const float* __restrict__ b1)
{
    int r = blockIdx.x;          // 0..RR-1, enumerates (b,m,k)
    int j = threadIdx.x;         // 0..255
    int b = r / (MM * KNN);
    int idx = g_knn[r];
    const float* f = feats + ((size_t)b * PP + idx) * 6;
    __shared__ float fs[6];
    if (j < 6) fs[j] = f[j];
    __syncthreads();
    float acc = b1[j];
#pragma unroll
    for (int t = 0; t < 6; t++) acc = fmaf(fs[t], W1[t * 256 + j], acc);
    g_bufA[(size_t)r * 256 + j] = fmaxf(acc, 0.f);
}

// ---------------- tiled SGEMM: C[Mr,N] = act(A[Mr,K] @ B[K,N] + bias) -------------
template<bool RELU>
__global__ __launch_bounds__(256, 2) void sgemm_kernel(
    const float* __restrict__ A, const float* __restrict__ B,
    const float* __restrict__ bias, float* __restrict__ C,
    int Mr, int N, int K)
{
    __shared__ float As[8][128];
    __shared__ float Bs[8][128];
    int tid = threadIdx.x;
    int bx = blockIdx.x, by = blockIdx.y;
    int tx = tid & 15, ty = tid >> 4;
    float acc[8][8];
#pragma unroll
    for (int i = 0; i < 8; i++)
#pragma unroll
        for (int j = 0; j < 8; j++) acc[i][j] = 0.f;

    int arow = tid >> 1;
    int acol = (tid & 1) << 2;
    int brow = tid >> 5;
    int bcol = (tid & 31) << 2;
    const float* Ap = A + ((size_t)(by * 128 + arow)) * K + acol;
    const float* Bp = B + (size_t)brow * N + bx * 128 + bcol;
    int nk = K >> 3;
    for (int kt = 0; kt < nk; kt++) {
        float4 av = *(const float4*)Ap;
        float4 bv = *(const float4*)Bp;
        As[acol + 0][arow] = av.x;
        As[acol + 1][arow] = av.y;
        As[acol + 2][arow] = av.z;
        As[acol + 3][arow] = av.w;
        *(float4*)&Bs[brow][bcol] = bv;
        __syncthreads();
#pragma unroll
        for (int kk = 0; kk < 8; kk++) {
            float a[8], bf[8];
            *(float4*)&a[0]  = *(const float4*)&As[kk][ty << 2];
            *(float4*)&a[4]  = *(const float4*)&As[kk][64 + (ty << 2)];
            *(float4*)&bf[0] = *(const float4*)&Bs[kk][tx << 2];
            *(float4*)&bf[4] = *(const float4*)&Bs[kk][64 + (tx << 2)];
#pragma unroll
            for (int i = 0; i < 8; i++)
#pragma unroll
                for (int j = 0; j < 8; j++)
                    acc[i][j] = fmaf(a[i], bf[j], acc[i][j]);
        }
        __syncthreads();
        Ap += 8;
        Bp += (size_t)8 * N;
    }
#pragma unroll
    for (int i = 0; i < 8; i++) {
        int r = by * 128 + ((i < 4) ? (ty * 4 + i) : (64 + ty * 4 + i - 4));
#pragma unroll
        for (int jh = 0; jh < 2; jh++) {
            int c = bx * 128 + jh * 64 + tx * 4;
            float vv[4];
#pragma unroll
            for (int j = 0; j < 4; j++) {
                float x = acc[i][jh * 4 + j] + bias[c + j];
                if (RELU) x = fmaxf(x, 0.f);
                vv[j] = x;
            }
            *(float4*)&C[(size_t)r * N + c] = make_float4(vv[0], vv[1], vv[2], vv[3]);
        }
    }
}

// ---------------- max-pool over K neighbors ---------------------------------------
__global__ __launch_bounds__(256) void maxpool_kernel()
{
    int i = blockIdx.x * 256 + threadIdx.x;      // over QQ*DD
    if (i >= QQ * DD) return;
    int q = i / DD, d = i % DD;
    const float* p = g_bufB + ((size_t)q * KNN) * DD + d;
    float v = p[0];
#pragma unroll
    for (int k = 1; k < KNN; k++) v = fmaxf(v, p[(size_t)k * DD]);
    g_pool[i] = v;
}

// ---------------- mask fill --------------------------------------------------------
__global__ void fill_mask(float* m)
{
    int i = blockIdx.x * 256 + threadIdx.x;
    if (i < QQ) m[i] = 1.0f;
}

// ---------------- launcher ---------------------------------------------------------
extern "C" void kernel_launch(void* const* d_in, const int* in_sizes, int n_in,
                              void* d_out, int out_size)
{
    const float* coords = (const float*)d_in[0];
    const float* feats  = (const float*)d_in[1];
    const float* W1 = (const float*)d_in[2];  const float* b1 = (const float*)d_in[3];
    const float* W2 = (const float*)d_in[4];  const float* b2 = (const float*)d_in[5];
    const float* W3 = (const float*)d_in[6];  const float* b3 = (const float*)d_in[7];
    const float* W4 = (const float*)d_in[8];  const float* b4 = (const float*)d_in[9];
    const float* Wa1 = (const float*)d_in[10]; const float* ba1 = (const float*)d_in[11];
    const float* Wa2 = (const float*)d_in[12]; const float* ba2 = (const float*)d_in[13];

    float* out     = (float*)d_out;
    float* tokens  = out;                               // [QQ, DD]
    float* centout = out + (size_t)QQ * DD;             // [QQ, 4]
    float* masks   = centout + (size_t)QQ * 4;          // [QQ]

    float *pA, *pB, *pPool, *pH;
    int* pKnn;
    cudaGetSymbolAddress((void**)&pA, g_bufA);
    cudaGetSymbolAddress((void**)&pB, g_bufB);
    cudaGetSymbolAddress((void**)&pPool, g_pool);
    cudaGetSymbolAddress((void**)&pH, g_h);
    cudaGetSymbolAddress((void**)&pKnn, g_knn);

    // 1. FPS -> centroids (scratch + output region)
    fps_kernel<<<BB, 1024>>>(coords, centout);

    // 2. kNN (64KB dynamic smem)
    cudaFuncSetAttribute(knn_kernel, cudaFuncAttributeMaxDynamicSharedMemorySize, PP * 8);
    knn_kernel<<<dim3(MM, BB), 256, PP * 8>>>(coords, pKnn);

    // 3. gather + layer1 (6 -> 256, relu) -> g_bufA
    gather_mlp1<<<RR, 256>>>(feats, W1, b1);

    // 4. MLP chain (only 32768 gathered rows, not all 131072 points)
    sgemm_kernel<true ><<<dim3(512 / 128, RR / 128), 256>>>(pA, W2, b2, pB, RR, 512, 256);
    sgemm_kernel<true ><<<dim3(768 / 128, RR / 128), 256>>>(pB, W3, b3, pA, RR, 768, 512);
    sgemm_kernel<false><<<dim3(768 / 128, RR / 128), 256>>>(pA, W4, b4, pB, RR, 768, 768);

    // 5. max-pool over K
    maxpool_kernel<<<(QQ * DD + 255) / 256, 256>>>();

    // 6. attention MLP -> tokens
    sgemm_kernel<true ><<<dim3(DD / 128, QQ / 128), 256>>>(pPool, Wa1, ba1, pH, QQ, DD, DD);
    sgemm_kernel<false><<<dim3(DD / 128, QQ / 128), 256>>>(pH, Wa2, ba2, tokens, QQ, DD, DD);

    // 7. masks
    fill_mask<<<(QQ + 255) / 256, 256>>>(masks);
}

// round 6
// speedup vs baseline: 2.0091x; 2.0091x over previous
#include <cuda_runtime.h>
#include <stdint.h>

#define BB 16
#define PP 8192
#define MM 128
#define KNN 16
#define DD 768
#define QQ (BB*MM)      // 2048 queries/tokens
#define RR (QQ*KNN)     // 32768 gathered rows

// ---------------- scratch (device globals; no allocation allowed) ----------------
__device__ float g_cent[QQ*4];
__device__ int   g_knn[RR];
__device__ float g_bufA[(size_t)RR*768];
__device__ float g_bufB[(size_t)RR*768];
__device__ float g_pool[(size_t)QQ*DD];
__device__ float g_h[(size_t)QQ*DD];
// transposed weights [N][K] (K-major so B operand is n-major/k-contiguous = "col" for mma)
#define OFF_W2T  0
#define OFF_W3T  (512*256)
#define OFF_W4T  (OFF_W3T + 768*512)
#define OFF_WA1T (OFF_W4T + 768*768)
#define OFF_WA2T (OFF_WA1T + 768*768)
__device__ float g_wt[OFF_WA2T + 768*768];

__device__ __forceinline__ uint32_t f2tf32(float x) {
    uint32_t u; asm("cvt.rn.tf32.f32 %0, %1;" : "=r"(u) : "f"(x)); return u;
}

// ---------------- FPS: one block per batch, points register-resident -------------
__global__ __launch_bounds__(1024) void fps_kernel(const float* __restrict__ coords,
                                                   float* __restrict__ cent_out2)
{
    int b = blockIdx.x;
    int tid = threadIdx.x;
    float px[8], py[8], pz[8], pw[8], dmin[8];
#pragma unroll
    for (int i = 0; i < 8; i++) {
        int p = tid + i * 1024;
        const float* c = coords + ((size_t)b * PP + p) * 5;
        px[i] = c[1]; py[i] = c[2]; pz[i] = c[3]; pw[i] = c[4];
        dmin[i] = 1e30f;
    }
    __shared__ float last[4];
    __shared__ unsigned long long red[32];
    __shared__ int cur_s;
    int cur = 0;
    for (int m = 0; m < MM; m++) {
        if (tid == (cur & 1023)) {
            int i = cur >> 10;
            last[0] = px[i]; last[1] = py[i]; last[2] = pz[i]; last[3] = pw[i];
            float* o  = g_cent + ((size_t)b * MM + m) * 4;
            o[0] = px[i]; o[1] = py[i]; o[2] = pz[i]; o[3] = pw[i];
            float* o2 = cent_out2 + ((size_t)b * MM + m) * 4;
            o2[0] = px[i]; o2[1] = py[i]; o2[2] = pz[i]; o2[3] = pw[i];
        }
        __syncthreads();
        if (m == MM - 1) break;
        float lx = last[0], ly = last[1], lz = last[2], lw = last[3];
        unsigned long long best = 0ull;
#pragma unroll
        for (int i = 0; i < 8; i++) {
            float dx = __fsub_rn(px[i], lx);
            float dy = __fsub_rn(py[i], ly);
            float dz = __fsub_rn(pz[i], lz);
            float dw = __fsub_rn(pw[i], lw);
            float d = __fadd_rn(__fadd_rn(__fadd_rn(__fmul_rn(dx,dx), __fmul_rn(dy,dy)),
                                          __fmul_rn(dz,dz)), __fmul_rn(dw,dw));
            float dm = fminf(dmin[i], d);
            dmin[i] = dm;
            unsigned long long key = ((unsigned long long)__float_as_uint(dm) << 32)
                                   | (unsigned)(0x7FFFFFFF - (tid + i * 1024));
            if (key > best) best = key;
        }
        for (int off = 16; off; off >>= 1) {
            unsigned long long o = __shfl_down_sync(0xFFFFFFFFu, best, off);
            if (o > best) best = o;
        }
        if ((tid & 31) == 0) red[tid >> 5] = best;
        __syncthreads();
        if (tid < 32) {
            unsigned long long v = red[tid];
            for (int off = 16; off; off >>= 1) {
                unsigned long long o = __shfl_down_sync(0xFFFFFFFFu, v, off);
                if (o > v) v = o;
            }
            if (tid == 0) cur_s = 0x7FFFFFFF - (int)(v & 0xFFFFFFFFu);
        }
        __syncthreads();
        cur = cur_s;
    }
}

// ---------------- kNN: one block per centroid, keys in 64KB smem ------------------
__global__ __launch_bounds__(256) void knn_kernel(const float* __restrict__ coords,
                                                  int* __restrict__ knn)
{
    extern __shared__ unsigned long long keys[];
    int m = blockIdx.x, b = blockIdx.y;
    int tid = threadIdx.x;
    const float* c = g_cent + ((size_t)b * MM + m) * 4;
    float c0 = c[0], c1 = c[1], c2 = c[2], c3 = c[3];
    float cen2 = __fadd_rn(__fadd_rn(__fadd_rn(__fmul_rn(c0,c0), __fmul_rn(c1,c1)),
                                     __fmul_rn(c2,c2)), __fmul_rn(c3,c3));
    for (int p = tid; p < PP; p += 256) {
        const float* q = coords + ((size_t)b * PP + p) * 5;
        float x0 = q[1], x1 = q[2], x2 = q[3], x3 = q[4];
        float pts2 = __fadd_rn(__fadd_rn(__fadd_rn(__fmul_rn(x0,x0), __fmul_rn(x1,x1)),
                                         __fmul_rn(x2,x2)), __fmul_rn(x3,x3));
        float dot  = __fadd_rn(__fadd_rn(__fadd_rn(__fmul_rn(c0,x0), __fmul_rn(c1,x1)),
                                         __fmul_rn(c2,x2)), __fmul_rn(c3,x3));
        float d2 = __fsub_rn(__fadd_rn(cen2, pts2), __fmul_rn(2.0f, dot));
        unsigned u = __float_as_uint(d2);
        u = (u & 0x80000000u) ? ~u : (u | 0x80000000u);
        keys[p] = ((unsigned long long)u << 32) | (unsigned)p;
    }
    __syncthreads();
    __shared__ unsigned long long red[8];
    for (int k = 0; k < KNN; k++) {
        unsigned long long best = ~0ull;
        for (int p = tid; p < PP; p += 256) {
            unsigned long long v = keys[p];
            if (v < best) best = v;
        }
        for (int off = 16; off; off >>= 1) {
            unsigned long long o = __shfl_down_sync(0xFFFFFFFFu, best, off);
            if (o < best) best = o;
        }
        if ((tid & 31) == 0) red[tid >> 5] = best;
        __syncthreads();
        if (tid == 0) {
            unsigned long long v = red[0];
            for (int w = 1; w < 8; w++) if (red[w] < v) v = red[w];
            int idx = (int)(v & 0xFFFFFFFFu);
            knn[((size_t)b * MM + m) * KNN + k] = idx;
            keys[idx] = ~0ull;
        }
        __syncthreads();
    }
}

// ---------------- gather + layer1 (6 -> 256, relu) --------------------------------
__global__ __launch_bounds__(256) void gather_mlp1(const float* __restrict__ feats,
                                                   const float* __restrict__ W1,
                                                   const float* __restrict__ b1)
{
    int r = blockIdx.x;
    int j = threadIdx.x;
    int b = r / (MM * KNN);
    int idx = g_knn[r];
    const float* f = feats + ((size_t)b * PP + idx) * 6;
    __shared__ float fs[6];
    if (j < 6) fs[j] = f[j];
    __syncthreads();
    float acc = b1[j];
#pragma unroll
    for (int t = 0; t < 6; t++) acc = fmaf(fs[t], W1[t * 256 + j], acc);
    g_bufA[(size_t)r * 256 + j] = fmaxf(acc, 0.f);
}

// ---------------- weight transpose: Wt[n][k] = W[k][n] -----------------------------
__global__ __launch_bounds__(256) void transpose_w(const float* __restrict__ W,
                                                   float* __restrict__ Wt, int K, int N)
{
    int i = blockIdx.x * 256 + threadIdx.x;
    if (i < K * N) {
        int k = i / N, n = i % N;
        Wt[(size_t)n * K + k] = W[i];
    }
}

// ================= tf32 mma.sync GEMM =============================================
// C[Mr,N] = act(A[Mr,K] @ Bt[N,K]^T + bias)    (Bt is [N][K], K contiguous)
// CTA tile 128x128. K staged in chunks of 32. Single smem buffer + reg staging.
// 8 warps: 4 (m) x 2 (n); warp tile 32x64 = 2 m16 x 8 n8 fragments of m16n8k8.
#define SPAD 36   // smem row stride in floats (pad 4): conflict-free, 16B-aligned

template<bool RELU>
__global__ __launch_bounds__(256) void mma_gemm(
    const float* __restrict__ A, const float* __restrict__ Bt,
    const float* __restrict__ bias, float* __restrict__ C,
    int N, int K)
{
    __shared__ uint32_t As[128 * SPAD];
    __shared__ uint32_t Bs[128 * SPAD];
    int tid = threadIdx.x, wid = tid >> 5, lane = tid & 31;
    int gid = lane >> 2, tig = lane & 3;
    int bx = blockIdx.x, by = blockIdx.y;
    int m_base = (wid & 3) * 32;
    int n_base = (wid >> 2) * 64;

    const float* Ag = A  + (size_t)(by * 128) * K;
    const float* Bg = Bt + (size_t)(bx * 128) * K;

    float acc[2][8][4];
#pragma unroll
    for (int mt = 0; mt < 2; mt++)
#pragma unroll
        for (int nt = 0; nt < 8; nt++)
#pragma unroll
            for (int j = 0; j < 4; j++) acc[mt][nt][j] = 0.f;

    // staging rows/cols for this thread (4 float4 per matrix per chunk)
    int srow[4], sc4[4];
#pragma unroll
    for (int r = 0; r < 4; r++) {
        int id = tid + 256 * r;
        srow[r] = id >> 3;
        sc4[r]  = id & 7;
    }

    // ---- prologue: fill chunk 0 ----
#pragma unroll
    for (int r = 0; r < 4; r++) {
        float4 va = *(const float4*)(Ag + (size_t)srow[r] * K + sc4[r] * 4);
        float4 vb = *(const float4*)(Bg + (size_t)srow[r] * K + sc4[r] * 4);
        int si = srow[r] * SPAD + sc4[r] * 4;
        *(uint4*)&As[si] = make_uint4(f2tf32(va.x), f2tf32(va.y), f2tf32(va.z), f2tf32(va.w));
        *(uint4*)&Bs[si] = make_uint4(f2tf32(vb.x), f2tf32(vb.y), f2tf32(vb.z), f2tf32(vb.w));
    }
    __syncthreads();

    int NC = K >> 5;
    uint4 sa[4], sb[4];
    for (int c = 0; c < NC; c++) {
        bool more = (c + 1 < NC);
        if (more) {
            int kb = (c + 1) << 5;
#pragma unroll
            for (int r = 0; r < 4; r++) {
                float4 va = *(const float4*)(Ag + (size_t)srow[r] * K + kb + sc4[r] * 4);
                float4 vb = *(const float4*)(Bg + (size_t)srow[r] * K + kb + sc4[r] * 4);
                sa[r] = make_uint4(f2tf32(va.x), f2tf32(va.y), f2tf32(va.z), f2tf32(va.w));
                sb[r] = make_uint4(f2tf32(vb.x), f2tf32(vb.y), f2tf32(vb.z), f2tf32(vb.w));
            }
        }
        // ---- compute on smem chunk c ----
#pragma unroll
        for (int ks = 0; ks < 4; ks++) {
            int k0 = ks * 8;
            uint32_t af[2][4];
#pragma unroll
            for (int mt = 0; mt < 2; mt++) {
                int row = m_base + mt * 16 + gid;
                af[mt][0] = As[row * SPAD + k0 + tig];
                af[mt][1] = As[(row + 8) * SPAD + k0 + tig];
                af[mt][2] = As[row * SPAD + k0 + tig + 4];
                af[mt][3] = As[(row + 8) * SPAD + k0 + tig + 4];
            }
#pragma unroll
            for (int nt = 0; nt < 8; nt++) {
                int col = n_base + nt * 8 + gid;
                uint32_t b0 = Bs[col * SPAD + k0 + tig];
                uint32_t b1 = Bs[col * SPAD + k0 + tig + 4];
#pragma unroll
                for (int mt = 0; mt < 2; mt++) {
                    asm volatile(
                        "mma.sync.aligned.m16n8k8.row.col.f32.tf32.tf32.f32 "
                        "{%0,%1,%2,%3}, {%4,%5,%6,%7}, {%8,%9}, {%0,%1,%2,%3};"
                        : "+f"(acc[mt][nt][0]), "+f"(acc[mt][nt][1]),
                          "+f"(acc[mt][nt][2]), "+f"(acc[mt][nt][3])
                        : "r"(af[mt][0]), "r"(af[mt][1]), "r"(af[mt][2]), "r"(af[mt][3]),
                          "r"(b0), "r"(b1));
                }
            }
        }
        if (more) {
            __syncthreads();
#pragma unroll
            for (int r = 0; r < 4; r++) {
                int si = srow[r] * SPAD + sc4[r] * 4;
                *(uint4*)&As[si] = sa[r];
                *(uint4*)&Bs[si] = sb[r];
            }
            __syncthreads();
        }
    }

    // ---- epilogue: bias + relu, direct global stores (float2 per fragment row) ----
#pragma unroll
    for (int nt = 0; nt < 8; nt++) {
        int cg = bx * 128 + n_base + nt * 8 + 2 * tig;
        float bz0 = bias[cg], bz1 = bias[cg + 1];
#pragma unroll
        for (int mt = 0; mt < 2; mt++) {
            int rg = by * 128 + m_base + mt * 16 + gid;
            float v0 = acc[mt][nt][0] + bz0;
            float v1 = acc[mt][nt][1] + bz1;
            float v2 = acc[mt][nt][2] + bz0;
            float v3 = acc[mt][nt][3] + bz1;
            if (RELU) {
                v0 = fmaxf(v0, 0.f); v1 = fmaxf(v1, 0.f);
                v2 = fmaxf(v2, 0.f); v3 = fmaxf(v3, 0.f);
            }
            *(float2*)(C + (size_t)rg * N + cg)       = make_float2(v0, v1);
            *(float2*)(C + (size_t)(rg + 8) * N + cg) = make_float2(v2, v3);
        }
    }
}

// ---------------- max-pool over K neighbors ---------------------------------------
__global__ __launch_bounds__(256) void maxpool_kernel()
{
    int i = blockIdx.x * 256 + threadIdx.x;
    if (i >= QQ * DD) return;
    int q = i / DD, d = i % DD;
    const float* p = g_bufB + ((size_t)q * KNN) * DD + d;
    float v = p[0];
#pragma unroll
    for (int k = 1; k < KNN; k++) v = fmaxf(v, p[(size_t)k * DD]);
    g_pool[i] = v;
}

// ---------------- mask fill --------------------------------------------------------
__global__ void fill_mask(float* m)
{
    int i = blockIdx.x * 256 + threadIdx.x;
    if (i < QQ) m[i] = 1.0f;
}

// ---------------- launcher ---------------------------------------------------------
extern "C" void kernel_launch(void* const* d_in, const int* in_sizes, int n_in,
                              void* d_out, int out_size)
{
    const float* coords = (const float*)d_in[0];
    const float* feats  = (const float*)d_in[1];
    const float* W1 = (const float*)d_in[2];  const float* b1 = (const float*)d_in[3];
    const float* W2 = (const float*)d_in[4];  const float* b2 = (const float*)d_in[5];
    const float* W3 = (const float*)d_in[6];  const float* b3 = (const float*)d_in[7];
    const float* W4 = (const float*)d_in[8];  const float* b4 = (const float*)d_in[9];
    const float* Wa1 = (const float*)d_in[10]; const float* ba1 = (const float*)d_in[11];
    const float* Wa2 = (const float*)d_in[12]; const float* ba2 = (const float*)d_in[13];

    float* out     = (float*)d_out;
    float* tokens  = out;                               // [QQ, DD]
    float* centout = out + (size_t)QQ * DD;             // [QQ, 4]
    float* masks   = centout + (size_t)QQ * 4;          // [QQ]

    float *pA, *pB, *pPool, *pH, *pWt;
    int* pKnn;
    cudaGetSymbolAddress((void**)&pA, g_bufA);
    cudaGetSymbolAddress((void**)&pB, g_bufB);
    cudaGetSymbolAddress((void**)&pPool, g_pool);
    cudaGetSymbolAddress((void**)&pH, g_h);
    cudaGetSymbolAddress((void**)&pKnn, g_knn);
    cudaGetSymbolAddress((void**)&pWt, g_wt);

    // 1. FPS -> centroids
    fps_kernel<<<BB, 1024>>>(coords, centout);

    // 2. kNN (64KB dynamic smem)
    cudaFuncSetAttribute(knn_kernel, cudaFuncAttributeMaxDynamicSharedMemorySize, PP * 8);
    knn_kernel<<<dim3(MM, BB), 256, PP * 8>>>(coords, pKnn);

    // 3. weight transposes
    transpose_w<<<(256 * 512 + 255) / 256, 256>>>(W2,  pWt + OFF_W2T,  256, 512);
    transpose_w<<<(512 * 768 + 255) / 256, 256>>>(W3,  pWt + OFF_W3T,  512, 768);
    transpose_w<<<(768 * 768 + 255) / 256, 256>>>(W4,  pWt + OFF_W4T,  768, 768);
    transpose_w<<<(768 * 768 + 255) / 256, 256>>>(Wa1, pWt + OFF_WA1T, 768, 768);
    transpose_w<<<(768 * 768 + 255) / 256, 256>>>(Wa2, pWt + OFF_WA2T, 768, 768);

    // 4. gather + layer1 (6 -> 256, relu) -> g_bufA
    gather_mlp1<<<RR, 256>>>(feats, W1, b1);

    // 5. MLP chain on tensor cores (tf32 mma.sync)
    mma_gemm<true ><<<dim3(512 / 128, RR / 128), 256>>>(pA, pWt + OFF_W2T, b2, pB, 512, 256);
    mma_gemm<true ><<<dim3(768 / 128, RR / 128), 256>>>(pB, pWt + OFF_W3T, b3, pA, 768, 512);
    mma_gemm<false><<<dim3(768 / 128, RR / 128), 256>>>(pA, pWt + OFF_W4T, b4, pB, 768, 768);

    // 6. max-pool over K
    maxpool_kernel<<<(QQ * DD + 255) / 256, 256>>>();

    // 7. attention MLP -> tokens
    mma_gemm<true ><<<dim3(DD / 128, QQ / 128), 256>>>(pPool, pWt + OFF_WA1T, ba1, pH, 768, 768);
    mma_gemm<false><<<dim3(DD / 128, QQ / 128), 256>>>(pH, pWt + OFF_WA2T, ba2, tokens, 768, 768);

    // 8. masks
    fill_mask<<<(QQ + 255) / 256, 256>>>(masks);
}

// round 7
// speedup vs baseline: 2.3275x; 1.1585x over previous
#include <cuda_runtime.h>
#include <stdint.h>

#define BB 16
#define PP 8192
#define MM 128
#define KNN 16
#define DD 768
#define QQ (BB*MM)      // 2048 queries/tokens
#define RR (QQ*KNN)     // 32768 gathered rows

// ---------------- scratch (device globals; no allocation allowed) ----------------
__device__ float g_cent[QQ*4];
__device__ int   g_knn[RR];
__device__ float g_bufA[(size_t)RR*768];
__device__ float g_bufB[(size_t)RR*768];
__device__ float g_pool[(size_t)QQ*DD];
__device__ float g_h[(size_t)QQ*DD];
// transposed weights [N][K] (K-major so B operand is n-major/k-contiguous = "col" for mma)
#define OFF_W2T  0
#define OFF_W3T  (512*256)
#define OFF_W4T  (OFF_W3T + 768*512)
#define OFF_WA1T (OFF_W4T + 768*768)
#define OFF_WA2T (OFF_WA1T + 768*768)
__device__ float g_wt[OFF_WA2T + 768*768];

__device__ __forceinline__ uint32_t f2tf32(float x) {
    uint32_t u; asm("cvt.rn.tf32.f32 %0, %1;" : "=r"(u) : "f"(x)); return u;
}
__device__ __forceinline__ float tf32r(float x) {
    return __uint_as_float(f2tf32(x));
}

// ---------------- FPS: one block per batch, points register-resident -------------
__global__ __launch_bounds__(1024) void fps_kernel(const float* __restrict__ coords,
                                                   float* __restrict__ cent_out2)
{
    int b = blockIdx.x;
    int tid = threadIdx.x;
    float px[8], py[8], pz[8], pw[8], dmin[8];
#pragma unroll
    for (int i = 0; i < 8; i++) {
        int p = tid + i * 1024;
        const float* c = coords + ((size_t)b * PP + p) * 5;
        px[i] = c[1]; py[i] = c[2]; pz[i] = c[3]; pw[i] = c[4];
        dmin[i] = 1e30f;
    }
    __shared__ float last[4];
    __shared__ unsigned long long red[32];
    __shared__ int cur_s;
    int cur = 0;
    for (int m = 0; m < MM; m++) {
        if (tid == (cur & 1023)) {
            int i = cur >> 10;
            last[0] = px[i]; last[1] = py[i]; last[2] = pz[i]; last[3] = pw[i];
            float* o  = g_cent + ((size_t)b * MM + m) * 4;
            o[0] = px[i]; o[1] = py[i]; o[2] = pz[i]; o[3] = pw[i];
            float* o2 = cent_out2 + ((size_t)b * MM + m) * 4;
            o2[0] = px[i]; o2[1] = py[i]; o2[2] = pz[i]; o2[3] = pw[i];
        }
        __syncthreads();
        if (m == MM - 1) break;
        float lx = last[0], ly = last[1], lz = last[2], lw = last[3];
        unsigned long long best = 0ull;
#pragma unroll
        for (int i = 0; i < 8; i++) {
            float dx = __fsub_rn(px[i], lx);
            float dy = __fsub_rn(py[i], ly);
            float dz = __fsub_rn(pz[i], lz);
            float dw = __fsub_rn(pw[i], lw);
            float d = __fadd_rn(__fadd_rn(__fadd_rn(__fmul_rn(dx,dx), __fmul_rn(dy,dy)),
                                          __fmul_rn(dz,dz)), __fmul_rn(dw,dw));
            float dm = fminf(dmin[i], d);
            dmin[i] = dm;
            unsigned long long key = ((unsigned long long)__float_as_uint(dm) << 32)
                                   | (unsigned)(0x7FFFFFFF - (tid + i * 1024));
            if (key > best) best = key;
        }
        for (int off = 16; off; off >>= 1) {
            unsigned long long o = __shfl_down_sync(0xFFFFFFFFu, best, off);
            if (o > best) best = o;
        }
        if ((tid & 31) == 0) red[tid >> 5] = best;
        __syncthreads();
        if (tid < 32) {
            unsigned long long v = red[tid];
            for (int off = 16; off; off >>= 1) {
                unsigned long long o = __shfl_down_sync(0xFFFFFFFFu, v, off);
                if (o > v) v = o;
            }
            if (tid == 0) cur_s = 0x7FFFFFFF - (int)(v & 0xFFFFFFFFu);
        }
        __syncthreads();
        cur = cur_s;
    }
}

// ---------------- kNN: one block per centroid, keys in 64KB smem ------------------
__global__ __launch_bounds__(256) void knn_kernel(const float* __restrict__ coords,
                                                  int* __restrict__ knn)
{
    extern __shared__ unsigned long long keys[];
    int m = blockIdx.x, b = blockIdx.y;
    int tid = threadIdx.x;
    const float* c = g_cent + ((size_t)b * MM + m) * 4;
    float c0 = c[0], c1 = c[1], c2 = c[2], c3 = c[3];
    float cen2 = __fadd_rn(__fadd_rn(__fadd_rn(__fmul_rn(c0,c0), __fmul_rn(c1,c1)),
                                     __fmul_rn(c2,c2)), __fmul_rn(c3,c3));
    for (int p = tid; p < PP; p += 256) {
        const float* q = coords + ((size_t)b * PP + p) * 5;
        float x0 = q[1], x1 = q[2], x2 = q[3], x3 = q[4];
        float pts2 = __fadd_rn(__fadd_rn(__fadd_rn(__fmul_rn(x0,x0), __fmul_rn(x1,x1)),
                                         __fmul_rn(x2,x2)), __fmul_rn(x3,x3));
        float dot  = __fadd_rn(__fadd_rn(__fadd_rn(__fmul_rn(c0,x0), __fmul_rn(c1,x1)),
                                         __fmul_rn(c2,x2)), __fmul_rn(c3,x3));
        float d2 = __fsub_rn(__fadd_rn(cen2, pts2), __fmul_rn(2.0f, dot));
        unsigned u = __float_as_uint(d2);
        u = (u & 0x80000000u) ? ~u : (u | 0x80000000u);
        keys[p] = ((unsigned long long)u << 32) | (unsigned)p;
    }
    __syncthreads();
    __shared__ unsigned long long red[8];
    for (int k = 0; k < KNN; k++) {
        unsigned long long best = ~0ull;
        for (int p = tid; p < PP; p += 256) {
            unsigned long long v = keys[p];
            if (v < best) best = v;
        }
        for (int off = 16; off; off >>= 1) {
            unsigned long long o = __shfl_down_sync(0xFFFFFFFFu, best, off);
            if (o < best) best = o;
        }
        if ((tid & 31) == 0) red[tid >> 5] = best;
        __syncthreads();
        if (tid == 0) {
            unsigned long long v = red[0];
            for (int w = 1; w < 8; w++) if (red[w] < v) v = red[w];
            int idx = (int)(v & 0xFFFFFFFFu);
            knn[((size_t)b * MM + m) * KNN + k] = idx;
            keys[idx] = ~0ull;
        }
        __syncthreads();
    }
}

// ---------------- gather + layer1 (6 -> 256, relu), stores tf32-rounded ------------
__global__ __launch_bounds__(256) void gather_mlp1(const float* __restrict__ feats,
                                                   const float* __restrict__ W1,
                                                   const float* __restrict__ b1)
{
    int r = blockIdx.x;
    int j = threadIdx.x;
    int b = r / (MM * KNN);
    int idx = g_knn[r];
    const float* f = feats + ((size_t)b * PP + idx) * 6;
    __shared__ float fs[6];
    if (j < 6) fs[j] = f[j];
    __syncthreads();
    float acc = b1[j];
#pragma unroll
    for (int t = 0; t < 6; t++) acc = fmaf(fs[t], W1[t * 256 + j], acc);
    g_bufA[(size_t)r * 256 + j] = tf32r(fmaxf(acc, 0.f));
}

// ---------------- weight transpose: Wt[n][k] = round_tf32(W[k][n]) -----------------
__global__ __launch_bounds__(256) void transpose_w(const float* __restrict__ W,
                                                   float* __restrict__ Wt, int K, int N)
{
    int i = blockIdx.x * 256 + threadIdx.x;
    if (i < K * N) {
        int k = i / N, n = i % N;
        Wt[(size_t)n * K + k] = tf32r(W[i]);
    }
}

// ================= tf32 mma.sync GEMM, 3-stage cp.async pipeline ===================
// C[Mr,N] = act(A[Mr,K] @ Bt[N,K]^T + bias)    (A, Bt already tf32-rounded fp32)
// CTA tile 128x128. K staged in chunks of 32. 8 warps: 4(m) x 2(n), warp tile 32x64.
#define SPAD 36                      // smem row stride in words (conflict-free, 16B-OK)
#define STG_MAT (128 * SPAD * 4)     // 18432 B per matrix per stage
#define STG_BYTES (2 * STG_MAT)      // 36864 B per stage (A + B)
#define NSTAGE 3
#define GSMEM (NSTAGE * STG_BYTES)   // 110592 B

__device__ __forceinline__ void cp16(uint32_t saddr, const void* g) {
    asm volatile("cp.async.cg.shared.global [%0], [%1], 16;" :: "r"(saddr), "l"(g));
}

template<bool RELU, bool ROUND>
__global__ __launch_bounds__(256) void mma_gemm(
    const float* __restrict__ A, const float* __restrict__ Bt,
    const float* __restrict__ bias, float* __restrict__ C,
    int N, int K)
{
    extern __shared__ char dsm[];
    uint32_t sbase = (uint32_t)__cvta_generic_to_shared(dsm);
    int tid = threadIdx.x, wid = tid >> 5, lane = tid & 31;
    int gid = lane >> 2, tig = lane & 3;
    int bx = blockIdx.x, by = blockIdx.y;
    int m_base = (wid & 3) * 32;
    int n_base = (wid >> 2) * 64;

    const float* Ag = A  + (size_t)(by * 128) * K;
    const float* Bg = Bt + (size_t)(bx * 128) * K;

    // per-thread staging slots: 4 x 16B per matrix per stage
    int srow[4], sc4[4];
#pragma unroll
    for (int r = 0; r < 4; r++) {
        int id = tid + 256 * r;
        srow[r] = id >> 3;
        sc4[r]  = id & 7;
    }

    float acc[2][8][4];
#pragma unroll
    for (int mt = 0; mt < 2; mt++)
#pragma unroll
        for (int nt = 0; nt < 8; nt++)
#pragma unroll
            for (int j = 0; j < 4; j++) acc[mt][nt][j] = 0.f;

    int NC = K >> 5;

    // ---- prologue: issue stages 0 and 1, one commit group each ----
#pragma unroll
    for (int s = 0; s < 2; s++) {
        int kb = s << 5;
        uint32_t stb = sbase + s * STG_BYTES;
#pragma unroll
        for (int r = 0; r < 4; r++) {
            uint32_t doff = (uint32_t)(srow[r] * (SPAD * 4) + sc4[r] * 16);
            cp16(stb + doff,           Ag + (size_t)srow[r] * K + kb + sc4[r] * 4);
            cp16(stb + STG_MAT + doff, Bg + (size_t)srow[r] * K + kb + sc4[r] * 4);
        }
        asm volatile("cp.async.commit_group;" ::: "memory");
    }

    for (int c = 0; c < NC; c++) {
        asm volatile("cp.async.wait_group 1;" ::: "memory");
        __syncthreads();

        // issue stage c+2 into buffer (c+2)%3 (consumed at iteration c-1; safe after sync)
        if (c + 2 < NC) {
            int kb = (c + 2) << 5;
            uint32_t stb = sbase + ((c + 2) % NSTAGE) * STG_BYTES;
#pragma unroll
            for (int r = 0; r < 4; r++) {
                uint32_t doff = (uint32_t)(srow[r] * (SPAD * 4) + sc4[r] * 16);
                cp16(stb + doff,           Ag + (size_t)srow[r] * K + kb + sc4[r] * 4);
                cp16(stb + STG_MAT + doff, Bg + (size_t)srow[r] * K + kb + sc4[r] * 4);
            }
        }
        asm volatile("cp.async.commit_group;" ::: "memory");   // empty group on tail keeps count aligned

        const uint32_t* As = (const uint32_t*)(dsm + (c % NSTAGE) * STG_BYTES);
        const uint32_t* Bs = As + 128 * SPAD;

#pragma unroll
        for (int ks = 0; ks < 4; ks++) {
            int k0 = ks * 8;
            uint32_t af[2][4];
#pragma unroll
            for (int mt = 0; mt < 2; mt++) {
                int row = m_base + mt * 16 + gid;
                af[mt][0] = As[row * SPAD + k0 + tig];
                af[mt][1] = As[(row + 8) * SPAD + k0 + tig];
                af[mt][2] = As[row * SPAD + k0 + tig + 4];
                af[mt][3] = As[(row + 8) * SPAD + k0 + tig + 4];
            }
#pragma unroll
            for (int nt = 0; nt < 8; nt++) {
                int col = n_base + nt * 8 + gid;
                uint32_t b0 = Bs[col * SPAD + k0 + tig];
                uint32_t b1 = Bs[col * SPAD + k0 + tig + 4];
#pragma unroll
                for (int mt = 0; mt < 2; mt++) {
                    asm volatile(
                        "mma.sync.aligned.m16n8k8.row.col.f32.tf32.tf32.f32 "
                        "{%0,%1,%2,%3}, {%4,%5,%6,%7}, {%8,%9}, {%0,%1,%2,%3};"
                        : "+f"(acc[mt][nt][0]), "+f"(acc[mt][nt][1]),
                          "+f"(acc[mt][nt][2]), "+f"(acc[mt][nt][3])
                        : "r"(af[mt][0]), "r"(af[mt][1]), "r"(af[mt][2]), "r"(af[mt][3]),
                          "r"(b0), "r"(b1));
                }
            }
        }
    }

    // ---- epilogue: bias + relu (+ tf32 rounding for intermediate layers) ----
#pragma unroll
    for (int nt = 0; nt < 8; nt++) {
        int cg = bx * 128 + n_base + nt * 8 + 2 * tig;
        float bz0 = bias[cg], bz1 = bias[cg + 1];
#pragma unroll
        for (int mt = 0; mt < 2; mt++) {
            int rg = by * 128 + m_base + mt * 16 + gid;
            float v0 = acc[mt][nt][0] + bz0;
            float v1 = acc[mt][nt][1] + bz1;
            float v2 = acc[mt][nt][2] + bz0;
            float v3 = acc[mt][nt][3] + bz1;
            if (RELU) {
                v0 = fmaxf(v0, 0.f); v1 = fmaxf(v1, 0.f);
                v2 = fmaxf(v2, 0.f); v3 = fmaxf(v3, 0.f);
            }
            if (ROUND) {
                v0 = tf32r(v0); v1 = tf32r(v1);
                v2 = tf32r(v2); v3 = tf32r(v3);
            }
            *(float2*)(C + (size_t)rg * N + cg)       = make_float2(v0, v1);
            *(float2*)(C + (size_t)(rg + 8) * N + cg) = make_float2(v2, v3);
        }
    }
}

// ---------------- max-pool over K neighbors (inputs tf32-rounded; max preserves) ---
__global__ __launch_bounds__(256) void maxpool_kernel()
{
    int i = blockIdx.x * 256 + threadIdx.x;
    if (i >= QQ * DD) return;
    int q = i / DD, d = i % DD;
    const float* p = g_bufB + ((size_t)q * KNN) * DD + d;
    float v = p[0];
#pragma unroll
    for (int k = 1; k < KNN; k++) v = fmaxf(v, p[(size_t)k * DD]);
    g_pool[i] = v;
}

// ---------------- mask fill --------------------------------------------------------
__global__ void fill_mask(float* m)
{
    int i = blockIdx.x * 256 + threadIdx.x;
    if (i < QQ) m[i] = 1.0f;
}

// ---------------- launcher ---------------------------------------------------------
extern "C" void kernel_launch(void* const* d_in, const int* in_sizes, int n_in,
                              void* d_out, int out_size)
{
    const float* coords = (const float*)d_in[0];
    const float* feats  = (const float*)d_in[1];
    const float* W1 = (const float*)d_in[2];  const float* b1 = (const float*)d_in[3];
    const float* W2 = (const float*)d_in[4];  const float* b2 = (const float*)d_in[5];
    const float* W3 = (const float*)d_in[6];  const float* b3 = (const float*)d_in[7];
    const float* W4 = (const float*)d_in[8];  const float* b4 = (const float*)d_in[9];
    const float* Wa1 = (const float*)d_in[10]; const float* ba1 = (const float*)d_in[11];
    const float* Wa2 = (const float*)d_in[12]; const float* ba2 = (const float*)d_in[13];

    float* out     = (float*)d_out;
    float* tokens  = out;                               // [QQ, DD]
    float* centout = out + (size_t)QQ * DD;             // [QQ, 4]
    float* masks   = centout + (size_t)QQ * 4;          // [QQ]

    float *pA, *pB, *pPool, *pH, *pWt;
    int* pKnn;
    cudaGetSymbolAddress((void**)&pA, g_bufA);
    cudaGetSymbolAddress((void**)&pB, g_bufB);
    cudaGetSymbolAddress((void**)&pPool, g_pool);
    cudaGetSymbolAddress((void**)&pH, g_h);
    cudaGetSymbolAddress((void**)&pKnn, g_knn);
    cudaGetSymbolAddress((void**)&pWt, g_wt);

    // 1. FPS -> centroids
    fps_kernel<<<BB, 1024>>>(coords, centout);

    // 2. kNN (64KB dynamic smem)
    cudaFuncSetAttribute(knn_kernel, cudaFuncAttributeMaxDynamicSharedMemorySize, PP * 8);
    knn_kernel<<<dim3(MM, BB), 256, PP * 8>>>(coords, pKnn);

    // 3. weight transposes (tf32-rounded)
    transpose_w<<<(256 * 512 + 255) / 256, 256>>>(W2,  pWt + OFF_W2T,  256, 512);
    transpose_w<<<(512 * 768 + 255) / 256, 256>>>(W3,  pWt + OFF_W3T,  512, 768);
    transpose_w<<<(768 * 768 + 255) / 256, 256>>>(W4,  pWt + OFF_W4T,  768, 768);
    transpose_w<<<(768 * 768 + 255) / 256, 256>>>(Wa1, pWt + OFF_WA1T, 768, 768);
    transpose_w<<<(768 * 768 + 255) / 256, 256>>>(Wa2, pWt + OFF_WA2T, 768, 768);

    // 4. gather + layer1 (6 -> 256, relu, tf32-rounded) -> g_bufA
    gather_mlp1<<<RR, 256>>>(feats, W1, b1);

    // 5. MLP chain on tensor cores (tf32 mma.sync, cp.async pipelined)
    cudaFuncSetAttribute((const void*)mma_gemm<true,  true >, cudaFuncAttributeMaxDynamicSharedMemorySize, GSMEM);
    cudaFuncSetAttribute((const void*)mma_gemm<false, true >, cudaFuncAttributeMaxDynamicSharedMemorySize, GSMEM);
    cudaFuncSetAttribute((const void*)mma_gemm<false, false>, cudaFuncAttributeMaxDynamicSharedMemorySize, GSMEM);
    mma_gemm<true,  true ><<<dim3(512 / 128, RR / 128), 256, GSMEM>>>(pA, pWt + OFF_W2T, b2, pB, 512, 256);
    mma_gemm<true,  true ><<<dim3(768 / 128, RR / 128), 256, GSMEM>>>(pB, pWt + OFF_W3T, b3, pA, 768, 512);
    mma_gemm<false, true ><<<dim3(768 / 128, RR / 128), 256, GSMEM>>>(pA, pWt + OFF_W4T, b4, pB, 768, 768);

    // 6. max-pool over K (keeps tf32-rounded values)
    maxpool_kernel<<<(QQ * DD + 255) / 256, 256>>>();

    // 7. attention MLP -> tokens
    mma_gemm<true,  true ><<<dim3(DD / 128, QQ / 128), 256, GSMEM>>>(pPool, pWt + OFF_WA1T, ba1, pH, 768, 768);
    mma_gemm<false, false><<<dim3(DD / 128, QQ / 128), 256, GSMEM>>>(pH, pWt + OFF_WA2T, ba2, tokens, 768, 768);

    // 8. masks
    fill_mask<<<(QQ + 255) / 256, 256>>>(masks);
}